// round 7
// baseline (speedup 1.0000x reference)
#include <cuda_runtime.h>
#include <cuda_fp16.h>
#include <math.h>
#include <float.h>
#include <stdint.h>

#define N 8192
#define D 128
#define BM 128
#define BN 128
#define NBLK (N / BM)                         // 64
#define TOT_TILES (NBLK * (NBLK + 1) / 2)     // 2080 upper-triangular tiles
#define NCTA 148
#define TBASE (TOT_TILES / NCTA)              // 14
#define TREM  (TOT_TILES - TBASE * NCTA)      // 8
#define MARGIN 0.05f
#define TS 272                // smem tile row stride bytes (128 fp16 + 8 pad)

// ---------------- device scratch ----------------
__device__ __half g_hi[N * D];
__device__ __half g_lo[N * D];
__device__ float g_sq[N];
__device__ unsigned g_dminP[N];   // ordered-uint: min dot over positives
__device__ unsigned g_dmaxN[N];   // ordered-uint: max dot over negatives

// ---------------- smem layout (bytes) ----------------
#define TILE_BYTES (128 * TS)                 // 34816
#define SM_A_HI    0
#define SM_A_LO    TILE_BYTES
#define SM_B(b)    (2 * TILE_BYTES + (b) * TILE_BYTES)
#define SM_LAB(b)  (4 * TILE_BYTES + (b) * 512)
#define SM_RED     (4 * TILE_BYTES + 1024)    // redmin[4][128], redmax[4][128]
#define SM_TOTAL   (SM_RED + 4096)

__device__ __forceinline__ uint32_t smem_u32(const void* p) {
    uint32_t a;
    asm("{ .reg .u64 t; cvta.to.shared.u64 t, %1; cvt.u32.u64 %0, t; }" : "=r"(a) : "l"(p));
    return a;
}
#define CP16(dst, src) \
    asm volatile("cp.async.cg.shared.global [%0], [%1], 16;" :: "r"(dst), "l"(src) : "memory")
#define CP_COMMIT() asm volatile("cp.async.commit_group;" ::: "memory")
#define CP_WAIT0()  asm volatile("cp.async.wait_group 0;" ::: "memory")

__device__ __forceinline__ void ldm_x4(uint32_t* r, uint32_t addr) {
    asm volatile("ldmatrix.sync.aligned.m8n8.x4.shared.b16 {%0,%1,%2,%3}, [%4];"
                 : "=r"(r[0]), "=r"(r[1]), "=r"(r[2]), "=r"(r[3]) : "r"(addr));
}
__device__ __forceinline__ void ldm_x2(uint32_t* r, uint32_t addr) {
    asm volatile("ldmatrix.sync.aligned.m8n8.x2.shared.b16 {%0,%1}, [%2];"
                 : "=r"(r[0]), "=r"(r[1]) : "r"(addr));
}
// fp32-accumulate HMMA (hi term)
__device__ __forceinline__ void mma_f32(float* c, const uint32_t* a, const uint32_t* b) {
    asm volatile(
        "mma.sync.aligned.m16n8k16.row.col.f32.f16.f16.f32 "
        "{%0,%1,%2,%3}, {%4,%5,%6,%7}, {%8,%9}, {%0,%1,%2,%3};"
        : "+f"(c[0]), "+f"(c[1]), "+f"(c[2]), "+f"(c[3])
        : "r"(a[0]), "r"(a[1]), "r"(a[2]), "r"(a[3]), "r"(b[0]), "r"(b[1]));
}
// fp16-accumulate HMMA (lo correction term, 2x rate)
__device__ __forceinline__ void mma_f16acc(uint32_t* c, const uint32_t* a, const uint32_t* b) {
    asm volatile(
        "mma.sync.aligned.m16n8k16.row.col.f16.f16.f16.f16 "
        "{%0,%1}, {%2,%3,%4,%5}, {%6,%7}, {%0,%1};"
        : "+r"(c[0]), "+r"(c[1])
        : "r"(a[0]), "r"(a[1]), "r"(a[2]), "r"(a[3]), "r"(b[0]), "r"(b[1]));
}

__device__ __forceinline__ unsigned f2ord(float f) {
    unsigned b = __float_as_uint(f);
    return (b & 0x80000000u) ? ~b : (b | 0x80000000u);
}
__device__ __forceinline__ float ord2f(unsigned u) {
    unsigned b = (u & 0x80000000u) ? (u ^ 0x80000000u) : ~u;
    return __uint_as_float(b);
}
__device__ __forceinline__ int cumt(int r) { return r * NBLK - (r * (r - 1)) / 2; }

// ---------------------------------------------------------------------------
// Kernel 1: normalize rows -> fp16 hi/lo split + fp32 sumsq; init atomics.
__global__ void normalize_kernel(const float* __restrict__ x) {
    int row  = blockIdx.x * 8 + (threadIdx.x >> 5);
    int lane = threadIdx.x & 31;
    float4 v = ((const float4*)(x + (size_t)row * D))[lane];
    float s = v.x * v.x + v.y * v.y + v.z * v.z + v.w * v.w;
#pragma unroll
    for (int o = 16; o; o >>= 1) s += __shfl_xor_sync(0xffffffffu, s, o);
    float r = 1.0f / fmaxf(sqrtf(s), 1e-12f);
    float o4[4] = {v.x * r, v.y * r, v.z * r, v.w * r};
    float s2 = o4[0]*o4[0] + o4[1]*o4[1] + o4[2]*o4[2] + o4[3]*o4[3];
#pragma unroll
    for (int o = 16; o; o >>= 1) s2 += __shfl_xor_sync(0xffffffffu, s2, o);
    if (lane == 0) {
        g_sq[row] = s2;
        g_dminP[row] = f2ord(FLT_MAX);
        g_dmaxN[row] = f2ord(-FLT_MAX);
    }
    uint32_t hp[2], lp[2];
#pragma unroll
    for (int i = 0; i < 2; i++) {
        __half h0 = __float2half_rn(o4[2*i]);
        __half h1 = __float2half_rn(o4[2*i+1]);
        __half l0 = __float2half_rn(o4[2*i]   - __half2float(h0));
        __half l1 = __float2half_rn(o4[2*i+1] - __half2float(h1));
        hp[i] = (uint32_t)__half_as_ushort(h0) | ((uint32_t)__half_as_ushort(h1) << 16);
        lp[i] = (uint32_t)__half_as_ushort(l0) | ((uint32_t)__half_as_ushort(l1) << 16);
    }
    ((uint2*)(g_hi + (size_t)row * D))[lane] = make_uint2(hp[0], hp[1]);
    ((uint2*)(g_lo + (size_t)row * D))[lane] = make_uint2(lp[0], lp[1]);
}

// ---------------------------------------------------------------------------
// Kernel 2: persistent fused GEMM + batch-hard mining over the upper triangle.
// Mining is done on dot directly: hardest-pos = min dot (same label),
// hardest-neg = max dot (diff label). Self-pair auto-excluded (dot=1 = max).
__global__ __launch_bounds__(256, 1)
void tile_kernel(const int* __restrict__ labels) {
    extern __shared__ char smem[];
    const uint32_t sb = smem_u32(smem);
    const int tid  = threadIdx.x;
    const int lane = tid & 31;
    const int wid  = tid >> 5;
    const int wm   = wid & 1;      // 2 warp rows (64 each)
    const int wn   = wid >> 1;     // 4 warp cols (32 each)
    const int bid  = blockIdx.x;

    const int start = bid * TBASE + min(bid, TREM);
    const int tend  = start + TBASE + (bid < TREM ? 1 : 0);

    const uint32_t aLane = (uint32_t)((wm * 64 + (lane & 7) + ((lane >> 3) & 1) * 8) * TS
                                      + (lane >> 4) * 16);
    const int lane16 = lane & 15;
    const uint32_t bLane = (uint32_t)((wn * 32 + (lane16 & 7)) * TS + (lane16 >> 3) * 16);

    auto loadA = [&](int rowBase) {
        const char* sH = (const char*)g_hi + (size_t)rowBase * D * 2;
        const char* sL = (const char*)g_lo + (size_t)rowBase * D * 2;
#pragma unroll
        for (int i = 0; i < 8; i++) {
            int q = tid + i * 256;
            int r = q >> 4, kc = q & 15;
            uint32_t off = r * TS + kc * 16;
            size_t   go  = (size_t)r * 256 + kc * 16;
            CP16(sb + SM_A_HI + off, sH + go);
            CP16(sb + SM_A_LO + off, sL + go);
        }
    };
    auto loadB = [&](int ct, int b) {
        int colBase = ct * BN;
        const char* sH = (const char*)g_hi + (size_t)colBase * D * 2;
#pragma unroll
        for (int i = 0; i < 8; i++) {
            int q = tid + i * 256;
            int r = q >> 4, kc = q & 15;
            CP16(sb + SM_B(b) + r * TS + kc * 16, sH + (size_t)r * 256 + kc * 16);
        }
        if (tid < BN)
            *(int*)(smem + SM_LAB(b) + tid * 4) = labels[colBase + tid];
        CP_COMMIT();
    };

    int t = start;
    int rt = 0;
    while (cumt(rt + 1) <= t) rt++;

    while (t < tend) {
        const int rowBase = rt * BM;
        const int segEnd = min(tend, cumt(rt + 1));
        const int ct0 = rt + (t - cumt(rt));

        loadA(rowBase);
        loadB(ct0, 0);
        CP_WAIT0();
        __syncthreads();

        int rowlab[4][2];
#pragma unroll
        for (int mt = 0; mt < 4; mt++)
#pragma unroll
            for (int h = 0; h < 2; h++)
                rowlab[mt][h] = labels[rowBase + wm * 64 + mt * 16 + h * 8 + (lane >> 2)];

        // row-anchor running extrema (accumulated across the rt segment)
        float rminP[4][2], rmaxN[4][2];
#pragma unroll
        for (int mt = 0; mt < 4; mt++)
#pragma unroll
            for (int h = 0; h < 2; h++) { rminP[mt][h] = FLT_MAX; rmaxN[mt][h] = -FLT_MAX; }

        for (int tt = t; tt < segEnd; tt++) {
            const int ct = rt + (tt - cumt(rt));
            const int b  = (tt - t) & 1;
            if (tt + 1 < segEnd) loadB(ct + 1, b ^ 1);

            float    accH[4][4][4];
            uint32_t accL[4][4][2];
#pragma unroll
            for (int mt = 0; mt < 4; mt++)
#pragma unroll
                for (int nt = 0; nt < 4; nt++) {
#pragma unroll
                    for (int i = 0; i < 4; i++) accH[mt][nt][i] = 0.0f;
                    accL[mt][nt][0] = 0u; accL[mt][nt][1] = 0u;
                }

            const uint32_t AH = sb + SM_A_HI, AL = sb + SM_A_LO, BB = sb + SM_B(b);
#pragma unroll
            for (int ks = 0; ks < 8; ks++) {
                uint32_t aH[4][4], aL[4][4], bH[4][2];
#pragma unroll
                for (int mt = 0; mt < 4; mt++) {
                    uint32_t off = aLane + (uint32_t)(mt * 16 * TS + ks * 32);
                    ldm_x4(aH[mt], AH + off);
                    ldm_x4(aL[mt], AL + off);
                }
#pragma unroll
                for (int nt = 0; nt < 4; nt++)
                    ldm_x2(bH[nt], BB + bLane + (uint32_t)(nt * 8 * TS + ks * 32));
#pragma unroll
                for (int mt = 0; mt < 4; mt++)
#pragma unroll
                    for (int nt = 0; nt < 4; nt++) {
                        mma_f32(accH[mt][nt], aH[mt], bH[nt]);
                        mma_f16acc(accL[mt][nt], aL[mt], bH[nt]);
                    }
            }

            // epilogue: mine dot extrema for rows AND columns
            const int* labS = (const int*)(smem + SM_LAB(b));
            float cminP[4][2], cmaxN[4][2];
#pragma unroll
            for (int nt = 0; nt < 4; nt++)
#pragma unroll
                for (int c = 0; c < 2; c++) { cminP[nt][c] = FLT_MAX; cmaxN[nt][c] = -FLT_MAX; }

#pragma unroll
            for (int nt = 0; nt < 4; nt++) {
                int nl0 = wn * 32 + nt * 8 + 2 * (lane & 3);
                int lb0 = labS[nl0], lb1 = labS[nl0 + 1];
#pragma unroll
                for (int mt = 0; mt < 4; mt++)
#pragma unroll
                    for (int h = 0; h < 2; h++) {
                        float2 lo = __half22float2(
                            *reinterpret_cast<__half2*>(&accL[mt][nt][h]));
                        float d0 = accH[mt][nt][2 * h]     + lo.x;
                        float d1 = accH[mt][nt][2 * h + 1] + lo.y;
                        int rl = rowlab[mt][h];
                        if (rl == lb0) {
                            rminP[mt][h] = fminf(rminP[mt][h], d0);
                            cminP[nt][0] = fminf(cminP[nt][0], d0);
                        } else {
                            rmaxN[mt][h] = fmaxf(rmaxN[mt][h], d0);
                            cmaxN[nt][0] = fmaxf(cmaxN[nt][0], d0);
                        }
                        if (rl == lb1) {
                            rminP[mt][h] = fminf(rminP[mt][h], d1);
                            cminP[nt][1] = fminf(cminP[nt][1], d1);
                        } else {
                            rmaxN[mt][h] = fmaxf(rmaxN[mt][h], d1);
                            cmaxN[nt][1] = fmaxf(cmaxN[nt][1], d1);
                        }
                    }
            }

            // column flush (uniform; diag redundancy is harmless)
#pragma unroll
            for (int nt = 0; nt < 4; nt++)
#pragma unroll
                for (int c = 0; c < 2; c++)
#pragma unroll
                    for (int off = 4; off <= 16; off <<= 1) {
                        cminP[nt][c] = fminf(cminP[nt][c], __shfl_xor_sync(0xffffffffu, cminP[nt][c], off));
                        cmaxN[nt][c] = fmaxf(cmaxN[nt][c], __shfl_xor_sync(0xffffffffu, cmaxN[nt][c], off));
                    }
            if (lane < 4) {
                int colBase = ct * BN;
#pragma unroll
                for (int nt = 0; nt < 4; nt++)
#pragma unroll
                    for (int c = 0; c < 2; c++) {
                        int cg = colBase + wn * 32 + nt * 8 + 2 * lane + c;
                        atomicMin(&g_dminP[cg], f2ord(cminP[nt][c]));
                        atomicMax(&g_dmaxN[cg], f2ord(cmaxN[nt][c]));
                    }
            }

            if (tt + 1 < segEnd) CP_WAIT0();
            __syncthreads();
        }

        // row-anchor flush for this rt segment
#pragma unroll
        for (int mt = 0; mt < 4; mt++)
#pragma unroll
            for (int h = 0; h < 2; h++)
#pragma unroll
                for (int off = 1; off <= 2; off <<= 1) {
                    rminP[mt][h] = fminf(rminP[mt][h], __shfl_xor_sync(0xffffffffu, rminP[mt][h], off));
                    rmaxN[mt][h] = fmaxf(rmaxN[mt][h], __shfl_xor_sync(0xffffffffu, rmaxN[mt][h], off));
                }
        float* redmin = (float*)(smem + SM_RED);   // [4][128]
        float* redmax = redmin + 4 * 128;
        if ((lane & 3) == 0) {
#pragma unroll
            for (int mt = 0; mt < 4; mt++)
#pragma unroll
                for (int h = 0; h < 2; h++) {
                    int rl = wm * 64 + mt * 16 + h * 8 + (lane >> 2);
                    redmin[wn * 128 + rl] = rminP[mt][h];
                    redmax[wn * 128 + rl] = rmaxN[mt][h];
                }
        }
        __syncthreads();
        if (tid < BM) {
            float mn = FLT_MAX, mx = -FLT_MAX;
#pragma unroll
            for (int w = 0; w < 4; w++) {
                mn = fminf(mn, redmin[w * 128 + tid]);
                mx = fmaxf(mx, redmax[w * 128 + tid]);
            }
            atomicMin(&g_dminP[rowBase + tid], f2ord(mn));
            atomicMax(&g_dmaxN[rowBase + tid], f2ord(mx));
        }
        __syncthreads();
        t = segEnd;
        rt++;
    }
}

// ---------------------------------------------------------------------------
// Kernel 3: per-anchor loss + AvgNonZero reduction.
// d^2 = sq_i + 1 - 2*dot  (sq_j ~ 1 within 1e-7 for normalized rows)
__global__ void finalize_kernel(float* __restrict__ out) {
    __shared__ float ssum[1024];
    __shared__ int   scnt[1024];
    int t = threadIdx.x;
    float sum = 0.0f;
    int   cnt = 0;
    for (int i = t; i < N; i += 1024) {
        float mp = ord2f(g_dminP[i]);   // min dot over positives
        float mn = ord2f(g_dmaxN[i]);   // max dot over negatives
        float sqi = g_sq[i];
        float dap = sqrtf(fmaxf(sqi + 1.0f - 2.0f * mp, 0.0f));
        float dan = sqrtf(fmaxf(sqi + 1.0f - 2.0f * mn, 0.0f));
        float per = fmaxf(dap - dan + MARGIN, 0.0f);
        if (per > 0.0f) { sum += per; cnt++; }
    }
    ssum[t] = sum; scnt[t] = cnt;
    __syncthreads();
    for (int o = 512; o; o >>= 1) {
        if (t < o) { ssum[t] += ssum[t + o]; scnt[t] += scnt[t + o]; }
        __syncthreads();
    }
    if (t == 0) out[0] = (scnt[0] > 0) ? (ssum[0] / (float)scnt[0]) : 0.0f;
}

// ---------------------------------------------------------------------------
extern "C" void kernel_launch(void* const* d_in, const int* in_sizes, int n_in,
                              void* d_out, int out_size) {
    const float* x      = (const float*)d_in[0];
    const int*   labels = (const int*)d_in[1];

    normalize_kernel<<<N / 8, 256>>>(x);

    cudaFuncSetAttribute(tile_kernel,
                         cudaFuncAttributeMaxDynamicSharedMemorySize, SM_TOTAL);
    tile_kernel<<<NCTA, 256, SM_TOTAL>>>(labels);

    finalize_kernel<<<1, 1024>>>((float*)d_out);
}